// round 2
// baseline (speedup 1.0000x reference)
#include <cuda_runtime.h>
#include <cuda_bf16.h>
#include <cstdint>

#define MAXN 100000
#define MAXE 1600000
#define DIN 256
#define F 64
#define TC 128  // 2*F combined columns

// ---------------- scratch (static device globals; no runtime alloc) ------
__device__ float  g_h [(size_t)MAXN * TC];   // [N][128]: cols 0..63 = h_high, 64..127 = h_low (post-leaky)
__device__ float  g_hp[(size_t)MAXN * TC];   // accumulators
__device__ float4 g_sc4[MAXN];               // per-node (s_hs, s_hd, s_ls, s_ld)
__device__ float2 g_rs[MAXN];                // (rowsum_high, rowsum_low)
__device__ float4 g_C[TC];                   // per-column folded coefficients
__device__ float  g_par[4];                  // inv_norm_high, inv_norm_low, theta_high, theta_low

__device__ __forceinline__ float lk(float x) { return x >= 0.0f ? x : 0.2f * x; }

__device__ __forceinline__ unsigned long long ffma2(unsigned long long a,
                                                    unsigned long long b,
                                                    unsigned long long c) {
    unsigned long long d;
    asm("fma.rn.f32x2 %0, %1, %2, %3;" : "=l"(d) : "l"(a), "l"(b), "l"(c));
    return d;
}

// ---------------- K0: fold coefficients, norms, thetas -------------------
__global__ void k_prep(const float* __restrict__ ah, const float* __restrict__ al,
                       const float* __restrict__ ch, const float* __restrict__ cl) {
    __shared__ float sh[256], sl[256];
    int t = threadIdx.x;
    float vh = ah[t], vl = al[t];
    sh[t] = vh * vh;
    sl[t] = vl * vl;
    __syncthreads();
    for (int o = 128; o > 0; o >>= 1) {
        if (t < o) { sh[t] += sh[t + o]; sl[t] += sl[t + o]; }
        __syncthreads();
    }
    if (t == 0) {
        g_par[0] = 1.0f / sqrtf(sh[0]);
        g_par[1] = 1.0f / sqrtf(sl[0]);
        g_par[2] = (fminf(fmaxf(ch[0] + 3.0f, 0.0f), 6.0f) / 3.0f + 1e-6f) * 0.5f;
        g_par[3] = (fminf(fmaxf(cl[0] + 3.0f, 0.0f), 6.0f) / 3.0f + 1e-6f) * 0.5f;
    }
    if (t < F) {
        float a0 = ah[t], a1 = ah[F + t], a2 = ah[2 * F + t], a3 = ah[3 * F + t];
        g_C[t] = make_float4(a0 + a2 + a3,   // s_hs coefficient
                             a1 + a2 - a3,   // s_hd coefficient
                             al[t],          // s_ls contribution from h_high
                             al[F + t]);     // s_ld contribution from h_high
    } else if (t < TC) {
        int c = t - F;
        float b2 = al[2 * F + c], b3 = al[3 * F + c];
        g_C[t] = make_float4(0.0f, 0.0f, b2 + b3, b2 - b3);  // low-h columns
    }
}

// ---------------- K1: zero accumulators ----------------------------------
__global__ void k_zero(int N) {
    int i = blockIdx.x * blockDim.x + threadIdx.x;
    if (i < N * (TC / 4)) reinterpret_cast<float4*>(g_hp)[i] = make_float4(0.f, 0.f, 0.f, 0.f);
    if (i < N) g_rs[i] = make_float2(0.f, 0.f);
}

// ---------------- K2: fused GEMM (FFMA2 / f32x2) + leaky + score scalars --
// 64 rows per block, 256 threads.
// smem: sIn [64][256] f32 (64KB) + sW2 packed (W[2k],W[2k+1]) per col: [128 k2][128 col] float2 (128KB).
// Lane tx owns columns {tx, tx+32, tx+64, tx+96} -> conflict-free LDS.64 on B.
// Accumulators hold (even-k, odd-k) partial sums, folded in the epilogue.
__global__ __launch_bounds__(256, 1) void k_gemm(const float* __restrict__ input,
                                                 const float* __restrict__ Wh,
                                                 const float* __restrict__ Wl, int N) {
    extern __shared__ float smem[];
    float* sIn = smem;              // [64][256]
    float* sW2 = smem + 64 * DIN;   // float2-packed: float index (k2*TC + col)*2 + parity
    int tid = threadIdx.x;
    int base = blockIdx.x * 64;

    // load + pack W: for each (k, col) write W[k][col] into sW2[(k/2)*TC + col].parity(k&1)
    // cols 0..63 <- Wh, 64..127 <- Wl
    for (int idx = tid; idx < DIN * 32; idx += 256) {
        int k = idx >> 5;
        int g = idx & 31;           // 32 groups of 4 cols = 128 cols
        int c4 = g * 4;
        float4 v;
        if (g < 16) v = *reinterpret_cast<const float4*>(&Wh[k * F + c4]);
        else        v = *reinterpret_cast<const float4*>(&Wl[k * F + (c4 - F)]);
        int k2 = k >> 1, par = k & 1;
        float* dst = &sW2[(k2 * TC + c4) * 2 + par];
        dst[0] = v.x; dst[2] = v.y; dst[4] = v.z; dst[6] = v.w;
    }
    // load input tile
    for (int idx = tid; idx < 64 * 64; idx += 256) {
        int r = idx >> 6;
        int k4 = (idx & 63) * 4;
        int n = base + r;
        float4 v = make_float4(0.f, 0.f, 0.f, 0.f);
        if (n < N) v = *reinterpret_cast<const float4*>(&input[(size_t)n * DIN + k4]);
        *reinterpret_cast<float4*>(&sIn[r * DIN + k4]) = v;
    }
    __syncthreads();

    int tx = tid & 31, ty = tid >> 5;  // lane, warp
    const float* aBase = &sIn[ty * 8 * DIN];

    unsigned long long acc[8][4];
#pragma unroll
    for (int j = 0; j < 8; j++)
#pragma unroll
        for (int c = 0; c < 4; c++) acc[j][c] = 0ull;

#pragma unroll 2
    for (int k2 = 0; k2 < DIN / 2; k2++) {
        unsigned long long b[4];
#pragma unroll
        for (int c = 0; c < 4; c++)
            b[c] = *reinterpret_cast<const unsigned long long*>(
                &sW2[(k2 * TC + tx + c * 32) * 2]);
#pragma unroll
        for (int j = 0; j < 8; j++) {
            unsigned long long a = *reinterpret_cast<const unsigned long long*>(
                &aBase[j * DIN + 2 * k2]);  // broadcast across lanes
            acc[j][0] = ffma2(a, b[0], acc[j][0]);
            acc[j][1] = ffma2(a, b[1], acc[j][1]);
            acc[j][2] = ffma2(a, b[2], acc[j][2]);
            acc[j][3] = ffma2(a, b[3], acc[j][3]);
        }
    }

    // epilogue: fold even/odd partials, leaky, store h, fold score scalars
    float C0x[4], C0y[4], C0z[4], C0w[4];
#pragma unroll
    for (int c = 0; c < 4; c++) {
        float4 C = g_C[tx + c * 32];
        C0x[c] = C.x; C0y[c] = C.y; C0z[c] = C.z; C0w[c] = C.w;
    }
#pragma unroll
    for (int j = 0; j < 8; j++) {
        int n = base + ty * 8 + j;
        float px = 0.f, py = 0.f, pz = 0.f, pw = 0.f;
        float hv[4];
#pragma unroll
        for (int c = 0; c < 4; c++) {
            float lo = __uint_as_float((unsigned)(acc[j][c] & 0xffffffffull));
            float hi = __uint_as_float((unsigned)(acc[j][c] >> 32));
            float h = lk(lo + hi);
            hv[c] = h;
            px += h * C0x[c];
            py += h * C0y[c];
            pz += h * C0z[c];
            pw += h * C0w[c];
        }
#pragma unroll
        for (int o = 16; o > 0; o >>= 1) {
            px += __shfl_down_sync(0xffffffffu, px, o);
            py += __shfl_down_sync(0xffffffffu, py, o);
            pz += __shfl_down_sync(0xffffffffu, pz, o);
            pw += __shfl_down_sync(0xffffffffu, pw, o);
        }
        if (n < N) {
#pragma unroll
            for (int c = 0; c < 4; c++)
                g_h[(size_t)n * TC + tx + c * 32] = hv[c];
            if (tx == 0) g_sc4[n] = make_float4(px, py, pz, pw);
        }
    }
}

// ---------------- K3: edge pass (one warp per edge) ----------------------
__global__ __launch_bounds__(256) void k_edge(const int* __restrict__ edge, int E) {
    int w = (blockIdx.x * blockDim.x + threadIdx.x) >> 5;
    int lane = threadIdx.x & 31;
    if (w >= E) return;
    int src = edge[w];
    int dst = edge[E + w];

    float4 ss = g_sc4[src];
    float4 sd = g_sc4[dst];
    float sh = (ss.x + sd.y) * g_par[0];
    float sl = (ss.z + sd.w) * g_par[1];
    float eh = __expf(-lk(sh));
    float el = __expf(-lk(sl));

    float4 hv = *reinterpret_cast<const float4*>(&g_h[(size_t)dst * TC + lane * 4]);
    float wgt = (lane < 16) ? eh : el;  // lanes 0-15: high cols, 16-31: low cols
    float vx = hv.x * wgt, vy = hv.y * wgt, vz = hv.z * wgt, vw = hv.w * wgt;

    float* p = &g_hp[(size_t)src * TC + lane * 4];
    asm volatile("red.global.add.v4.f32 [%0], {%1, %2, %3, %4};"
                 :: "l"(p), "f"(vx), "f"(vy), "f"(vz), "f"(vw)
                 : "memory");
    if (lane == 0) {
        asm volatile("red.global.add.v2.f32 [%0], {%1, %2};"
                     :: "l"(&g_rs[src]), "f"(eh), "f"(el)
                     : "memory");
    }
}

// ---------------- K4: normalize + leaky + write output -------------------
__global__ void k_out(float* __restrict__ out, int N) {
    int i = blockIdx.x * blockDim.x + threadIdx.x;
    if (i >= N * (TC / 4)) return;
    int n = i >> 5;
    int q = i & 31;
    float2 rs = g_rs[n];
    float denom = (q < 16) ? (rs.x + g_par[2]) : (rs.y + g_par[3]);
    float inv = 1.0f / denom;
    float4 v = *reinterpret_cast<const float4*>(&g_hp[(size_t)n * TC + q * 4]);
    v.x = lk(v.x * inv);
    v.y = lk(v.y * inv);
    v.z = lk(v.z * inv);
    v.w = lk(v.w * inv);
    *reinterpret_cast<float4*>(&out[(size_t)n * TC + q * 4]) = v;
}

// ---------------- launch --------------------------------------------------
extern "C" void kernel_launch(void* const* d_in, const int* in_sizes, int n_in,
                              void* d_out, int out_size) {
    const float* input = (const float*)d_in[0];
    const int*   edge  = (const int*)d_in[1];
    const float* Wh    = (const float*)d_in[2];
    const float* Wl    = (const float*)d_in[3];
    const float* ah    = (const float*)d_in[4];
    const float* al    = (const float*)d_in[5];
    const float* ch    = (const float*)d_in[6];
    const float* cl    = (const float*)d_in[7];
    float* out = (float*)d_out;

    int N = in_sizes[0] / DIN;
    int E = in_sizes[1] / 2;

    const int GEMM_SMEM = (64 * DIN + DIN * TC) * (int)sizeof(float);  // 192 KB
    cudaFuncSetAttribute(k_gemm, cudaFuncAttributeMaxDynamicSharedMemorySize, GEMM_SMEM);

    k_prep<<<1, 256>>>(ah, al, ch, cl);
    {
        int threads = N * (TC / 4);
        k_zero<<<(threads + 255) / 256, 256>>>(N);
    }
    k_gemm<<<(N + 63) / 64, 256, GEMM_SMEM>>>(input, Wh, Wl, N);
    k_edge<<<(E + 7) / 8, 256>>>(edge, E);
    k_out<<<(N * (TC / 4) + 255) / 256, 256>>>(out, N);
}

// round 3
// speedup vs baseline: 1.1237x; 1.1237x over previous
#include <cuda_runtime.h>
#include <cuda_bf16.h>
#include <cstdint>

#define MAXN 100000
#define MAXE 1600000
#define DIN 256
#define F 64
#define TC 128  // 2*F combined columns

// ---------------- scratch (static device globals; no runtime alloc) ------
__device__ float  g_h [(size_t)MAXN * TC];   // [N][128]: 0..63 h_high, 64..127 h_low (post-leaky)
__device__ float4 g_sc4[MAXN];               // per-node (s_hs, s_hd, s_ls, s_ld)
__device__ float4 g_C[TC];                   // per-column folded coefficients
__device__ float  g_par[4];                  // inv_norm_h, inv_norm_l, theta_h, theta_l
__device__ int    g_cnt[MAXN];               // per-src degree (histogram)
__device__ int    g_cur[MAXN];               // scatter cursors
__device__ int    g_off[MAXN + 1];           // CSR offsets
__device__ int    g_sorted[MAXE];            // dst ids grouped by src

__device__ __forceinline__ float lk(float x) { return x >= 0.0f ? x : 0.2f * x; }

// ---------------- K0: fold coefficients, norms, thetas -------------------
__global__ void k_prep(const float* __restrict__ ah, const float* __restrict__ al,
                       const float* __restrict__ ch, const float* __restrict__ cl) {
    __shared__ float sh[256], sl[256];
    int t = threadIdx.x;
    float vh = ah[t], vl = al[t];
    sh[t] = vh * vh;
    sl[t] = vl * vl;
    __syncthreads();
    for (int o = 128; o > 0; o >>= 1) {
        if (t < o) { sh[t] += sh[t + o]; sl[t] += sl[t + o]; }
        __syncthreads();
    }
    if (t == 0) {
        g_par[0] = 1.0f / sqrtf(sh[0]);
        g_par[1] = 1.0f / sqrtf(sl[0]);
        g_par[2] = (fminf(fmaxf(ch[0] + 3.0f, 0.0f), 6.0f) / 3.0f + 1e-6f) * 0.5f;
        g_par[3] = (fminf(fmaxf(cl[0] + 3.0f, 0.0f), 6.0f) / 3.0f + 1e-6f) * 0.5f;
    }
    if (t < F) {
        float a0 = ah[t], a1 = ah[F + t], a2 = ah[2 * F + t], a3 = ah[3 * F + t];
        g_C[t] = make_float4(a0 + a2 + a3,   // s_hs coeff
                             a1 + a2 - a3,   // s_hd coeff
                             al[t],          // s_ls from h_high
                             al[F + t]);     // s_ld from h_high
    } else if (t < TC) {
        int c = t - F;
        float b2 = al[2 * F + c], b3 = al[3 * F + c];
        g_C[t] = make_float4(0.0f, 0.0f, b2 + b3, b2 - b3);
    }
}

// ---------------- K1: zero sort counters ---------------------------------
__global__ void k_zc(int N) {
    int i = blockIdx.x * blockDim.x + threadIdx.x;
    if (i < N) { g_cnt[i] = 0; g_cur[i] = 0; }
}

// ---------------- K2: histogram of src -----------------------------------
__global__ void k_hist(const int* __restrict__ edge, int E) {
    int i = blockIdx.x * blockDim.x + threadIdx.x;
    if (i < E) atomicAdd(&g_cnt[edge[i]], 1);
}

// ---------------- K3: exclusive scan (single block, 1024 threads) --------
__global__ void k_scan(int N) {
    __shared__ int ssum[1024];
    int t = threadIdx.x;
    int chunk = (N + 1023) >> 10;
    int beg = t * chunk;
    int en = min(beg + chunk, N);
    int s = 0;
    for (int i = beg; i < en; i++) s += g_cnt[i];
    ssum[t] = s;
    __syncthreads();
    // Hillis-Steele inclusive scan
    for (int o = 1; o < 1024; o <<= 1) {
        int v = (t >= o) ? ssum[t - o] : 0;
        __syncthreads();
        ssum[t] += v;
        __syncthreads();
    }
    int run = (t == 0) ? 0 : ssum[t - 1];
    for (int i = beg; i < en; i++) {
        int c = g_cnt[i];
        g_off[i] = run;
        run += c;
    }
    if (t == 1023) g_off[N] = ssum[1023];
}

// ---------------- K4: scatter dst into src-grouped order -----------------
__global__ void k_scatter(const int* __restrict__ edge, int E) {
    int i = blockIdx.x * blockDim.x + threadIdx.x;
    if (i < E) {
        int s = edge[i];
        int pos = g_off[s] + atomicAdd(&g_cur[s], 1);
        g_sorted[pos] = edge[E + i];
    }
}

// ---------------- K5: fused GEMM + leaky + per-node score scalars --------
// 64 rows/block, 512 threads (16 warps, 4 rows each).
// smem: sIn [64][256] (64KB) + sW [256][128] (128KB). 1 CTA/SM.
__global__ __launch_bounds__(512, 1) void k_gemm(const float* __restrict__ input,
                                                 const float* __restrict__ Wh,
                                                 const float* __restrict__ Wl, int N) {
    extern __shared__ float smem[];
    float* sIn = smem;              // [64][256]
    float* sW  = smem + 64 * DIN;   // [256][128]
    int tid = threadIdx.x;
    int base = blockIdx.x * 64;

    // load combined W: cols 0..63 <- Wh, 64..127 <- Wl
    for (int idx = tid; idx < DIN * 32; idx += 512) {
        int k = idx >> 5;
        int g = idx & 31;
        int c4 = g * 4;
        float4 v;
        if (g < 16) v = *reinterpret_cast<const float4*>(&Wh[k * F + c4]);
        else        v = *reinterpret_cast<const float4*>(&Wl[k * F + (c4 - F)]);
        *reinterpret_cast<float4*>(&sW[k * TC + c4]) = v;
    }
    // load input tile
    for (int idx = tid; idx < 64 * 64; idx += 512) {
        int r = idx >> 6;
        int k4 = (idx & 63) * 4;
        int n = base + r;
        float4 v = make_float4(0.f, 0.f, 0.f, 0.f);
        if (n < N) v = *reinterpret_cast<const float4*>(&input[(size_t)n * DIN + k4]);
        *reinterpret_cast<float4*>(&sIn[r * DIN + k4]) = v;
    }
    __syncthreads();

    int tx = tid & 31, ty = tid >> 5;  // lane, warp (0..15)
    const float* aBase = &sIn[ty * 4 * DIN];
    const float* bBase = &sW[tx * 4];

    float acc[4][4];
#pragma unroll
    for (int j = 0; j < 4; j++)
#pragma unroll
        for (int c = 0; c < 4; c++) acc[j][c] = 0.0f;

#pragma unroll 4
    for (int k = 0; k < DIN; k++) {
        float4 b = *reinterpret_cast<const float4*>(&bBase[k * TC]);
#pragma unroll
        for (int j = 0; j < 4; j++) {
            float a = aBase[j * DIN + k];  // warp-uniform broadcast
            acc[j][0] += a * b.x;
            acc[j][1] += a * b.y;
            acc[j][2] += a * b.z;
            acc[j][3] += a * b.w;
        }
    }

    float4 C0 = g_C[tx * 4 + 0], C1 = g_C[tx * 4 + 1],
           C2 = g_C[tx * 4 + 2], C3 = g_C[tx * 4 + 3];
#pragma unroll
    for (int j = 0; j < 4; j++) {
        int n = base + ty * 4 + j;
        float4 h;
        h.x = lk(acc[j][0]);
        h.y = lk(acc[j][1]);
        h.z = lk(acc[j][2]);
        h.w = lk(acc[j][3]);
        float4 p;
        p.x = h.x * C0.x + h.y * C1.x + h.z * C2.x + h.w * C3.x;
        p.y = h.x * C0.y + h.y * C1.y + h.z * C2.y + h.w * C3.y;
        p.z = h.x * C0.z + h.y * C1.z + h.z * C2.z + h.w * C3.z;
        p.w = h.x * C0.w + h.y * C1.w + h.z * C2.w + h.w * C3.w;
#pragma unroll
        for (int o = 16; o > 0; o >>= 1) {
            p.x += __shfl_down_sync(0xffffffffu, p.x, o);
            p.y += __shfl_down_sync(0xffffffffu, p.y, o);
            p.z += __shfl_down_sync(0xffffffffu, p.z, o);
            p.w += __shfl_down_sync(0xffffffffu, p.w, o);
        }
        if (n < N) {
            *reinterpret_cast<float4*>(&g_h[(size_t)n * TC + tx * 4]) = h;
            if (tx == 0) g_sc4[n] = p;
        }
    }
}

// ---------------- K6: per-src gather + epilogue (one warp per node) ------
__global__ __launch_bounds__(256) void k_gather(float* __restrict__ out, int N) {
    int w = (blockIdx.x * blockDim.x + threadIdx.x) >> 5;
    int lane = threadIdx.x & 31;
    if (w >= N) return;
    int src = w;
    int beg = g_off[src], end = g_off[src + 1];

    float4 ss = g_sc4[src];
    float p0 = g_par[0], p1 = g_par[1];

    float ax = 0.f, ay = 0.f, az = 0.f, aw = 0.f;
    float rs_h = 0.f, rs_l = 0.f;

    for (int b = beg; b < end; b += 32) {
        int m = end - b;
        if (m > 32) m = 32;
        int d = 0;
        float eh = 0.f, el = 0.f;
        if (lane < m) {
            d = g_sorted[b + lane];
            float4 sd = g_sc4[d];
            eh = __expf(-lk((ss.x + sd.y) * p0));
            el = __expf(-lk((ss.z + sd.w) * p1));
        }
        for (int j = 0; j < m; j++) {
            int dj   = __shfl_sync(0xffffffffu, d, j);
            float ej = __shfl_sync(0xffffffffu, eh, j);
            float fj = __shfl_sync(0xffffffffu, el, j);
            float4 hv = *reinterpret_cast<const float4*>(&g_h[(size_t)dj * TC + lane * 4]);
            float wg = (lane < 16) ? ej : fj;
            ax += wg * hv.x;
            ay += wg * hv.y;
            az += wg * hv.z;
            aw += wg * hv.w;
            rs_h += ej;
            rs_l += fj;
        }
    }

    float denom = (lane < 16) ? (rs_h + g_par[2]) : (rs_l + g_par[3]);
    float inv = 1.0f / denom;
    float4 v;
    v.x = lk(ax * inv);
    v.y = lk(ay * inv);
    v.z = lk(az * inv);
    v.w = lk(aw * inv);
    *reinterpret_cast<float4*>(&out[(size_t)src * TC + lane * 4]) = v;
}

// ---------------- launch --------------------------------------------------
extern "C" void kernel_launch(void* const* d_in, const int* in_sizes, int n_in,
                              void* d_out, int out_size) {
    const float* input = (const float*)d_in[0];
    const int*   edge  = (const int*)d_in[1];
    const float* Wh    = (const float*)d_in[2];
    const float* Wl    = (const float*)d_in[3];
    const float* ah    = (const float*)d_in[4];
    const float* al    = (const float*)d_in[5];
    const float* ch    = (const float*)d_in[6];
    const float* cl    = (const float*)d_in[7];
    float* out = (float*)d_out;

    int N = in_sizes[0] / DIN;
    int E = in_sizes[1] / 2;

    const int GEMM_SMEM = (64 * DIN + DIN * TC) * (int)sizeof(float);  // 192 KB
    cudaFuncSetAttribute(k_gemm, cudaFuncAttributeMaxDynamicSharedMemorySize, GEMM_SMEM);

    k_prep<<<1, 256>>>(ah, al, ch, cl);
    k_zc<<<(N + 255) / 256, 256>>>(N);
    k_hist<<<(E + 255) / 256, 256>>>(edge, E);
    k_scan<<<1, 1024>>>(N);
    k_scatter<<<(E + 255) / 256, 256>>>(edge, E);
    k_gemm<<<(N + 63) / 64, 512, GEMM_SMEM>>>(input, Wh, Wl, N);
    k_gather<<<(N * 32 + 255) / 256, 256>>>(out, N);
}

// round 4
// speedup vs baseline: 1.3032x; 1.1597x over previous
#include <cuda_runtime.h>
#include <cuda_bf16.h>
#include <cstdint>

#define MAXN 100000
#define MAXE 1600000
#define DIN 256
#define F 64
#define TC 128  // 2*F combined columns
#define SCAN_B 256
#define MAX_BLK ((MAXN + SCAN_B - 1) / SCAN_B)   // 391

// ---------------- scratch (static device globals; no runtime alloc) ------
__device__ float  g_h [(size_t)MAXN * TC];   // [N][128]: 0..63 h_high, 64..127 h_low (post-leaky)
__device__ float4 g_sc4[MAXN];               // per-node (s_hs, s_hd, s_ls, s_ld)
__device__ float4 g_C[TC];                   // per-column folded coefficients
__device__ float  g_par[4];                  // inv_norm_h, inv_norm_l, theta_h, theta_l
__device__ int    g_cnt[MAXN];               // per-src degree (histogram)
__device__ int    g_cur[MAXN];               // scatter cursors (init = g_off)
__device__ int    g_off[MAXN + 1];           // CSR offsets
__device__ int    g_bsum[MAX_BLK];           // per-block sums
__device__ int    g_boff[MAX_BLK];           // per-block exclusive offsets
__device__ int    g_sorted[MAXE];            // dst ids grouped by src

__device__ __forceinline__ float lk(float x) { return x >= 0.0f ? x : 0.2f * x; }

// ---------------- K0: fold coefficients, norms, thetas -------------------
__global__ void k_prep(const float* __restrict__ ah, const float* __restrict__ al,
                       const float* __restrict__ ch, const float* __restrict__ cl) {
    __shared__ float sh[256], sl[256];
    int t = threadIdx.x;
    float vh = ah[t], vl = al[t];
    sh[t] = vh * vh;
    sl[t] = vl * vl;
    __syncthreads();
    for (int o = 128; o > 0; o >>= 1) {
        if (t < o) { sh[t] += sh[t + o]; sl[t] += sl[t + o]; }
        __syncthreads();
    }
    if (t == 0) {
        g_par[0] = 1.0f / sqrtf(sh[0]);
        g_par[1] = 1.0f / sqrtf(sl[0]);
        g_par[2] = (fminf(fmaxf(ch[0] + 3.0f, 0.0f), 6.0f) / 3.0f + 1e-6f) * 0.5f;
        g_par[3] = (fminf(fmaxf(cl[0] + 3.0f, 0.0f), 6.0f) / 3.0f + 1e-6f) * 0.5f;
    }
    if (t < F) {
        float a0 = ah[t], a1 = ah[F + t], a2 = ah[2 * F + t], a3 = ah[3 * F + t];
        g_C[t] = make_float4(a0 + a2 + a3,   // s_hs coeff
                             a1 + a2 - a3,   // s_hd coeff
                             al[t],          // s_ls from h_high
                             al[F + t]);     // s_ld from h_high
    } else if (t < TC) {
        int c = t - F;
        float b2 = al[2 * F + c], b3 = al[3 * F + c];
        g_C[t] = make_float4(0.0f, 0.0f, b2 + b3, b2 - b3);
    }
}

// ---------------- K1: zero histogram -------------------------------------
__global__ void k_zc(int N) {
    int i = blockIdx.x * blockDim.x + threadIdx.x;
    if (i < N) g_cnt[i] = 0;
}

// ---------------- K2: histogram of src -----------------------------------
__global__ void k_hist(const int* __restrict__ edge, int E) {
    int i = blockIdx.x * blockDim.x + threadIdx.x;
    if (i < E) atomicAdd(&g_cnt[edge[i]], 1);
}

// ---------------- K3a: per-block reduce ----------------------------------
__global__ void k_scan1(int N) {
    __shared__ int s[SCAN_B];
    int t = threadIdx.x;
    int i = blockIdx.x * SCAN_B + t;
    s[t] = (i < N) ? g_cnt[i] : 0;
    __syncthreads();
    for (int o = SCAN_B / 2; o > 0; o >>= 1) {
        if (t < o) s[t] += s[t + o];
        __syncthreads();
    }
    if (t == 0) g_bsum[blockIdx.x] = s[0];
}

// ---------------- K3b: scan block sums (1 block) --------------------------
__global__ void k_scan2(int nb) {
    __shared__ int s[512];
    int t = threadIdx.x;
    s[t] = (t < nb) ? g_bsum[t] : 0;
    __syncthreads();
    for (int o = 1; o < 512; o <<= 1) {
        int v = (t >= o) ? s[t - o] : 0;
        __syncthreads();
        s[t] += v;
        __syncthreads();
    }
    if (t < nb) g_boff[t] = (t == 0) ? 0 : s[t - 1];
}

// ---------------- K3c: local scan + base; writes offsets & cursors --------
__global__ void k_scan3(int N) {
    __shared__ int s[SCAN_B];
    int t = threadIdx.x;
    int i = blockIdx.x * SCAN_B + t;
    int c = (i < N) ? g_cnt[i] : 0;
    s[t] = c;
    __syncthreads();
    // Hillis-Steele inclusive
    for (int o = 1; o < SCAN_B; o <<= 1) {
        int v = (t >= o) ? s[t - o] : 0;
        __syncthreads();
        s[t] += v;
        __syncthreads();
    }
    int base = g_boff[blockIdx.x];
    if (i < N) {
        int off = base + s[t] - c;  // exclusive
        g_off[i] = off;
        g_cur[i] = off;
        if (i == N - 1) g_off[N] = off + c;
    }
}

// ---------------- K4: scatter dst into src-grouped order -----------------
__global__ void k_scatter(const int* __restrict__ edge, int E) {
    int i = blockIdx.x * blockDim.x + threadIdx.x;
    if (i < E) {
        int s = edge[i];
        int pos = atomicAdd(&g_cur[s], 1);
        g_sorted[pos] = edge[E + i];
    }
}

// ---------------- K5: fused GEMM + leaky + per-node score scalars --------
// 64 rows/block, 512 threads (16 warps, 4 rows each).
// smem: sIn [64][256] (64KB) + sW [256][128] (128KB). 1 CTA/SM.
__global__ __launch_bounds__(512, 1) void k_gemm(const float* __restrict__ input,
                                                 const float* __restrict__ Wh,
                                                 const float* __restrict__ Wl, int N) {
    extern __shared__ float smem[];
    float* sIn = smem;              // [64][256]
    float* sW  = smem + 64 * DIN;   // [256][128]
    int tid = threadIdx.x;
    int base = blockIdx.x * 64;

    for (int idx = tid; idx < DIN * 32; idx += 512) {
        int k = idx >> 5;
        int g = idx & 31;
        int c4 = g * 4;
        float4 v;
        if (g < 16) v = *reinterpret_cast<const float4*>(&Wh[k * F + c4]);
        else        v = *reinterpret_cast<const float4*>(&Wl[k * F + (c4 - F)]);
        *reinterpret_cast<float4*>(&sW[k * TC + c4]) = v;
    }
    for (int idx = tid; idx < 64 * 64; idx += 512) {
        int r = idx >> 6;
        int k4 = (idx & 63) * 4;
        int n = base + r;
        float4 v = make_float4(0.f, 0.f, 0.f, 0.f);
        if (n < N) v = *reinterpret_cast<const float4*>(&input[(size_t)n * DIN + k4]);
        *reinterpret_cast<float4*>(&sIn[r * DIN + k4]) = v;
    }
    __syncthreads();

    int tx = tid & 31, ty = tid >> 5;
    const float* aBase = &sIn[ty * 4 * DIN];
    const float* bBase = &sW[tx * 4];

    float acc[4][4];
#pragma unroll
    for (int j = 0; j < 4; j++)
#pragma unroll
        for (int c = 0; c < 4; c++) acc[j][c] = 0.0f;

#pragma unroll 4
    for (int k = 0; k < DIN; k++) {
        float4 b = *reinterpret_cast<const float4*>(&bBase[k * TC]);
#pragma unroll
        for (int j = 0; j < 4; j++) {
            float a = aBase[j * DIN + k];
            acc[j][0] += a * b.x;
            acc[j][1] += a * b.y;
            acc[j][2] += a * b.z;
            acc[j][3] += a * b.w;
        }
    }

    float4 C0 = g_C[tx * 4 + 0], C1 = g_C[tx * 4 + 1],
           C2 = g_C[tx * 4 + 2], C3 = g_C[tx * 4 + 3];
#pragma unroll
    for (int j = 0; j < 4; j++) {
        int n = base + ty * 4 + j;
        float4 h;
        h.x = lk(acc[j][0]);
        h.y = lk(acc[j][1]);
        h.z = lk(acc[j][2]);
        h.w = lk(acc[j][3]);
        float4 p;
        p.x = h.x * C0.x + h.y * C1.x + h.z * C2.x + h.w * C3.x;
        p.y = h.x * C0.y + h.y * C1.y + h.z * C2.y + h.w * C3.y;
        p.z = h.x * C0.z + h.y * C1.z + h.z * C2.z + h.w * C3.z;
        p.w = h.x * C0.w + h.y * C1.w + h.z * C2.w + h.w * C3.w;
#pragma unroll
        for (int o = 16; o > 0; o >>= 1) {
            p.x += __shfl_down_sync(0xffffffffu, p.x, o);
            p.y += __shfl_down_sync(0xffffffffu, p.y, o);
            p.z += __shfl_down_sync(0xffffffffu, p.z, o);
            p.w += __shfl_down_sync(0xffffffffu, p.w, o);
        }
        if (n < N) {
            *reinterpret_cast<float4*>(&g_h[(size_t)n * TC + tx * 4]) = h;
            if (tx == 0) g_sc4[n] = p;
        }
    }
}

// ---------------- K6: per-src gather + epilogue (one warp per node) ------
__global__ __launch_bounds__(256) void k_gather(float* __restrict__ out, int N) {
    int w = (blockIdx.x * blockDim.x + threadIdx.x) >> 5;
    int lane = threadIdx.x & 31;
    if (w >= N) return;
    int src = w;
    int beg = g_off[src], end = g_off[src + 1];

    float4 ss = g_sc4[src];
    float p0 = g_par[0], p1 = g_par[1];

    float ax = 0.f, ay = 0.f, az = 0.f, aw = 0.f;
    float rs_h = 0.f, rs_l = 0.f;

    for (int b = beg; b < end; b += 32) {
        int m = end - b;
        if (m > 32) m = 32;
        int d = 0;
        float eh = 0.f, el = 0.f;
        if (lane < m) {
            d = g_sorted[b + lane];
            float4 sd = g_sc4[d];
            eh = __expf(-lk((ss.x + sd.y) * p0));
            el = __expf(-lk((ss.z + sd.w) * p1));
        }
        for (int j = 0; j < m; j++) {
            int dj   = __shfl_sync(0xffffffffu, d, j);
            float ej = __shfl_sync(0xffffffffu, eh, j);
            float fj = __shfl_sync(0xffffffffu, el, j);
            float4 hv = *reinterpret_cast<const float4*>(&g_h[(size_t)dj * TC + lane * 4]);
            float wg = (lane < 16) ? ej : fj;
            ax += wg * hv.x;
            ay += wg * hv.y;
            az += wg * hv.z;
            aw += wg * hv.w;
            rs_h += ej;
            rs_l += fj;
        }
    }

    float denom = (lane < 16) ? (rs_h + g_par[2]) : (rs_l + g_par[3]);
    float inv = 1.0f / denom;
    float4 v;
    v.x = lk(ax * inv);
    v.y = lk(ay * inv);
    v.z = lk(az * inv);
    v.w = lk(aw * inv);
    *reinterpret_cast<float4*>(&out[(size_t)src * TC + lane * 4]) = v;
}

// ---------------- launch --------------------------------------------------
extern "C" void kernel_launch(void* const* d_in, const int* in_sizes, int n_in,
                              void* d_out, int out_size) {
    const float* input = (const float*)d_in[0];
    const int*   edge  = (const int*)d_in[1];
    const float* Wh    = (const float*)d_in[2];
    const float* Wl    = (const float*)d_in[3];
    const float* ah    = (const float*)d_in[4];
    const float* al    = (const float*)d_in[5];
    const float* ch    = (const float*)d_in[6];
    const float* cl    = (const float*)d_in[7];
    float* out = (float*)d_out;

    int N = in_sizes[0] / DIN;
    int E = in_sizes[1] / 2;
    int nb = (N + SCAN_B - 1) / SCAN_B;

    const int GEMM_SMEM = (64 * DIN + DIN * TC) * (int)sizeof(float);  // 192 KB
    cudaFuncSetAttribute(k_gemm, cudaFuncAttributeMaxDynamicSharedMemorySize, GEMM_SMEM);

    k_prep<<<1, 256>>>(ah, al, ch, cl);
    k_zc<<<(N + 255) / 256, 256>>>(N);
    k_hist<<<(E + 255) / 256, 256>>>(edge, E);
    k_scan1<<<nb, SCAN_B>>>(N);
    k_scan2<<<1, 512>>>(nb);
    k_scan3<<<nb, SCAN_B>>>(N);
    k_scatter<<<(E + 255) / 256, 256>>>(edge, E);
    k_gemm<<<(N + 63) / 64, 512, GEMM_SMEM>>>(input, Wh, Wl, N);
    k_gather<<<(N * 32 + 255) / 256, 256>>>(out, N);
}

// round 6
// speedup vs baseline: 1.6575x; 1.2719x over previous
#include <cuda_runtime.h>
#include <cuda_bf16.h>
#include <cstdint>

#define MAXN 100000
#define MAXE 1600000
#define DIN 256
#define F 64
#define TC 128  // 2*F combined columns
#define SCAN_B 256
#define MAX_BLK ((MAXN + SCAN_B - 1) / SCAN_B)   // 391
#define KC 128   // K-chunk for MMA

// ---------------- scratch (static device globals; no runtime alloc) ------
__device__ float  g_h [(size_t)MAXN * TC];   // [N][128]: 0..63 h_high, 64..127 h_low (post-leaky)
__device__ float4 g_sc4[MAXN];               // per-node (s_hs, s_hd, s_ls, s_ld)
__device__ float4 g_C[TC];                   // per-column folded coefficients
__device__ float  g_par[4];                  // inv_norm_h, inv_norm_l, theta_h, theta_l
__device__ int    g_cnt[MAXN];               // per-src degree (histogram)
__device__ int    g_cur[MAXN];               // scatter cursors (init = g_off)
__device__ int    g_off[MAXN + 1];           // CSR offsets
__device__ int    g_bsum[MAX_BLK];           // per-block sums
__device__ int    g_boff[MAX_BLK];           // per-block exclusive offsets
__device__ int    g_sorted[MAXE];            // dst ids grouped by src
// pre-split, fragment-ordered W images: [chunk][hi/lo][16 nt][8 ks][32 lane][2 reg][2 half] bf16
__device__ __align__(16) __nv_bfloat16 g_Wimg[2][2][16384];

__device__ __forceinline__ float lk(float x) { return x >= 0.0f ? x : 0.2f * x; }

// HMMA m16n8k16 bf16 (family-common PTX; tcgen05 unavailable at compute_103)
__device__ __forceinline__ void mma16816(float* c, const uint32_t* a, const uint32_t* b) {
    asm volatile(
        "mma.sync.aligned.m16n8k16.row.col.f32.bf16.bf16.f32 "
        "{%0,%1,%2,%3}, {%4,%5,%6,%7}, {%8,%9}, {%0,%1,%2,%3};"
        : "+f"(c[0]), "+f"(c[1]), "+f"(c[2]), "+f"(c[3])
        : "r"(a[0]), "r"(a[1]), "r"(a[2]), "r"(a[3]), "r"(b[0]), "r"(b[1]));
}

__device__ __forceinline__ uint32_t pack_bf16x2(float e0, float e1) {
    __nv_bfloat162 h2 = __floats2bfloat162_rn(e0, e1);  // (lo=e0, hi=e1)
    return *reinterpret_cast<uint32_t*>(&h2);
}

// ---------------- K0: fold coefficients, norms, thetas -------------------
__global__ void k_prep(const float* __restrict__ ah, const float* __restrict__ al,
                       const float* __restrict__ ch, const float* __restrict__ cl) {
    __shared__ float sh[256], sl[256];
    int t = threadIdx.x;
    float vh = ah[t], vl = al[t];
    sh[t] = vh * vh;
    sl[t] = vl * vl;
    __syncthreads();
    for (int o = 128; o > 0; o >>= 1) {
        if (t < o) { sh[t] += sh[t + o]; sl[t] += sl[t + o]; }
        __syncthreads();
    }
    if (t == 0) {
        g_par[0] = 1.0f / sqrtf(sh[0]);
        g_par[1] = 1.0f / sqrtf(sl[0]);
        g_par[2] = (fminf(fmaxf(ch[0] + 3.0f, 0.0f), 6.0f) / 3.0f + 1e-6f) * 0.5f;
        g_par[3] = (fminf(fmaxf(cl[0] + 3.0f, 0.0f), 6.0f) / 3.0f + 1e-6f) * 0.5f;
    }
    if (t < F) {
        float a0 = ah[t], a1 = ah[F + t], a2 = ah[2 * F + t], a3 = ah[3 * F + t];
        g_C[t] = make_float4(a0 + a2 + a3, a1 + a2 - a3, al[t], al[F + t]);
    } else if (t < TC) {
        int c = t - F;
        float b2 = al[2 * F + c], b3 = al[3 * F + c];
        g_C[t] = make_float4(0.0f, 0.0f, b2 + b3, b2 - b3);
    }
}

// ---------------- K0b: split W + store in HMMA fragment order ------------
// B fragment (m16n8k16, col-major = [n][k]): reg0 @ k=(lane%4)*2, reg1 @ k+8, n=lane/4.
__global__ void k_wprep(const float* __restrict__ Wh, const float* __restrict__ Wl) {
    int i = blockIdx.x * blockDim.x + threadIdx.x;  // 32768 = 256 k x 128 n
    if (i >= DIN * TC) return;
    int k = i >> 7;       // 0..255
    int n = i & 127;      // output col / B row
    float w = (n < F) ? Wh[k * F + n] : Wl[k * F + (n - F)];
    __nv_bfloat16 hi = __float2bfloat16(w);
    float rem = w - __bfloat162float(hi);
    __nv_bfloat16 lo = __float2bfloat16(rem);
    int c  = k >> 7;
    int kk = k & 127;
    int ks = kk >> 4;
    int kr = kk & 15;
    int nt = n >> 3;
    int lane = (n & 7) * 4 + ((kr & 7) >> 1);
    int reg  = kr >> 3;
    int half = kr & 1;
    int idx = ((((nt * 8 + ks) * 32 + lane) * 2 + reg) * 2 + half);
    g_Wimg[c][0][idx] = hi;
    g_Wimg[c][1][idx] = lo;
}

// ---------------- K1: zero histogram -------------------------------------
__global__ void k_zc(int N) {
    int i = blockIdx.x * blockDim.x + threadIdx.x;
    if (i < N) g_cnt[i] = 0;
}

// ---------------- K2: histogram of src -----------------------------------
__global__ void k_hist(const int* __restrict__ edge, int E) {
    int i = blockIdx.x * blockDim.x + threadIdx.x;
    if (i < E) atomicAdd(&g_cnt[edge[i]], 1);
}

// ---------------- K3a: per-block reduce ----------------------------------
__global__ void k_scan1(int N) {
    __shared__ int s[SCAN_B];
    int t = threadIdx.x;
    int i = blockIdx.x * SCAN_B + t;
    s[t] = (i < N) ? g_cnt[i] : 0;
    __syncthreads();
    for (int o = SCAN_B / 2; o > 0; o >>= 1) {
        if (t < o) s[t] += s[t + o];
        __syncthreads();
    }
    if (t == 0) g_bsum[blockIdx.x] = s[0];
}

// ---------------- K3b: scan block sums (1 block) --------------------------
__global__ void k_scan2(int nb) {
    __shared__ int s[512];
    int t = threadIdx.x;
    s[t] = (t < nb) ? g_bsum[t] : 0;
    __syncthreads();
    for (int o = 1; o < 512; o <<= 1) {
        int v = (t >= o) ? s[t - o] : 0;
        __syncthreads();
        s[t] += v;
        __syncthreads();
    }
    if (t < nb) g_boff[t] = (t == 0) ? 0 : s[t - 1];
}

// ---------------- K3c: local scan + base ----------------------------------
__global__ void k_scan3(int N) {
    __shared__ int s[SCAN_B];
    int t = threadIdx.x;
    int i = blockIdx.x * SCAN_B + t;
    int c = (i < N) ? g_cnt[i] : 0;
    s[t] = c;
    __syncthreads();
    for (int o = 1; o < SCAN_B; o <<= 1) {
        int v = (t >= o) ? s[t - o] : 0;
        __syncthreads();
        s[t] += v;
        __syncthreads();
    }
    int base = g_boff[blockIdx.x];
    if (i < N) {
        int off = base + s[t] - c;
        g_off[i] = off;
        g_cur[i] = off;
        if (i == N - 1) g_off[N] = off + c;
    }
}

// ---------------- K4: scatter dst into src-grouped order -----------------
__global__ void k_scatter(const int* __restrict__ edge, int E) {
    int i = blockIdx.x * blockDim.x + threadIdx.x;
    if (i < E) {
        int s = edge[i];
        int pos = atomicAdd(&g_cur[s], 1);
        g_sorted[pos] = edge[E + i];
    }
}

// ---------------- K5: split-bf16 HMMA GEMM + leaky + scores --------------
// 128 rows/CTA, 512 threads (16 warps: warp_m = wid%4 -> 32 rows, warp_n = wid/4 -> 32 cols).
// D = Ah*Wh + Ah*Wl + Al*Wh accumulated in fp32 fragments.
// smem: sAh(32K) sAl(32K) sWh(32K) sWl(32K) = 128 KB; h-buffer (64K) reuses sAh/sAl.
#define SAH 0
#define SAL 32768
#define SWH 65536
#define SWL 98304
#define MM_SMEM 131072

__global__ __launch_bounds__(512, 1) void k_mm(const float* __restrict__ input, int N) {
    extern __shared__ char sm[];
    uint32_t* sAh = reinterpret_cast<uint32_t*>(sm + SAH);
    uint32_t* sAl = reinterpret_cast<uint32_t*>(sm + SAL);
    uint32_t* sWh = reinterpret_cast<uint32_t*>(sm + SWH);
    uint32_t* sWl = reinterpret_cast<uint32_t*>(sm + SWL);

    int tid = threadIdx.x, wid = tid >> 5, lane = tid & 31;
    int base = blockIdx.x * 128;
    int warp_m = wid & 3, warp_n = wid >> 2;

    // staging role: row = tid/4 (0..127), kseg = tid%4 (32 k each)
    int srow = tid >> 2;
    int kseg = tid & 3;
    bool valid = (base + srow) < N;
    const float* ain = input + (size_t)(base + srow) * DIN;
    int s_mt = srow >> 4, s_r16 = srow & 15;

    float acc[2][4][4];
#pragma unroll
    for (int mt = 0; mt < 2; mt++)
#pragma unroll
        for (int nt = 0; nt < 4; nt++)
#pragma unroll
            for (int e = 0; e < 4; e++) acc[mt][nt][e] = 0.0f;

    for (int c = 0; c < 2; c++) {
        if (c == 1) __syncthreads();  // all frag reads of chunk 0 done

        // stage W fragment images (hi/lo): 2048 float4 each
        {
            const float4* wh4 = reinterpret_cast<const float4*>(g_Wimg[c][0]);
            const float4* wl4 = reinterpret_cast<const float4*>(g_Wimg[c][1]);
            float4* dwh = reinterpret_cast<float4*>(sWh);
            float4* dwl = reinterpret_cast<float4*>(sWl);
#pragma unroll
            for (int i = 0; i < 4; i++) {
                dwh[tid + i * 512] = wh4[tid + i * 512];
                dwl[tid + i * 512] = wl4[tid + i * 512];
            }
        }
        // stage A: load fp32, split to bf16 hi/lo, write in fragment order
#pragma unroll
        for (int j = 0; j < 8; j++) {
            int k4 = kseg * 8 + j;
            float4 v = make_float4(0.f, 0.f, 0.f, 0.f);
            if (valid) v = *reinterpret_cast<const float4*>(&ain[c * KC + k4 * 4]);
            float vv[4] = {v.x, v.y, v.z, v.w};
#pragma unroll
            for (int pp = 0; pp < 2; pp++) {   // two even-k pairs per float4
                int kp = k4 * 4 + pp * 2;      // even k within chunk
                float e0 = vv[pp * 2], e1 = vv[pp * 2 + 1];
                __nv_bfloat16 h0 = __float2bfloat16(e0), h1 = __float2bfloat16(e1);
                float r0 = e0 - __bfloat162float(h0), r1 = e1 - __bfloat162float(h1);
                uint32_t hiw = pack_bf16x2(__bfloat162float(h0), __bfloat162float(h1));
                uint32_t low = pack_bf16x2(r0, r1);
                int ks = kp >> 4, kr = kp & 15;
                int ln = (s_r16 & 7) * 4 + ((kr & 7) >> 1);
                int rg = (s_r16 >> 3) + 2 * (kr >> 3);
                int idx = ((s_mt * 8 + ks) * 32 + ln) * 4 + rg;
                sAh[idx] = hiw;
                sAl[idx] = low;
            }
        }
        __syncthreads();

        // MMA loop
#pragma unroll
        for (int ks = 0; ks < 8; ks++) {
            uint32_t Ah[2][4], Al[2][4], Bh[4][2], Bl[4][2];
#pragma unroll
            for (int mt = 0; mt < 2; mt++) {
                int mtg = warp_m * 2 + mt;
                uint4 a = *reinterpret_cast<const uint4*>(&sAh[((mtg * 8 + ks) * 32 + lane) * 4]);
                Ah[mt][0] = a.x; Ah[mt][1] = a.y; Ah[mt][2] = a.z; Ah[mt][3] = a.w;
                uint4 b = *reinterpret_cast<const uint4*>(&sAl[((mtg * 8 + ks) * 32 + lane) * 4]);
                Al[mt][0] = b.x; Al[mt][1] = b.y; Al[mt][2] = b.z; Al[mt][3] = b.w;
            }
#pragma unroll
            for (int nt = 0; nt < 4; nt++) {
                int ntg = warp_n * 4 + nt;
                uint2 h = *reinterpret_cast<const uint2*>(&sWh[((ntg * 8 + ks) * 32 + lane) * 2]);
                Bh[nt][0] = h.x; Bh[nt][1] = h.y;
                uint2 l = *reinterpret_cast<const uint2*>(&sWl[((ntg * 8 + ks) * 32 + lane) * 2]);
                Bl[nt][0] = l.x; Bl[nt][1] = l.y;
            }
#pragma unroll
            for (int mt = 0; mt < 2; mt++)
#pragma unroll
                for (int nt = 0; nt < 4; nt++) {
                    mma16816(acc[mt][nt], Ah[mt], Bh[nt]);
                    mma16816(acc[mt][nt], Ah[mt], Bl[nt]);
                    mma16816(acc[mt][nt], Al[mt], Bh[nt]);
                }
        }
    }
    __syncthreads();

    // epilogue: fragments -> smem h-buffer (leaky applied), reuse sAh/sAl (64 KB)
    float* hb = reinterpret_cast<float*>(sm);
    {
        int r0 = warp_m * 32 + (lane >> 2);
        int c0 = warp_n * 32 + (lane & 3) * 2;
#pragma unroll
        for (int mt = 0; mt < 2; mt++)
#pragma unroll
            for (int nt = 0; nt < 4; nt++) {
                int rr = r0 + mt * 16;
                int cc = c0 + nt * 8;
                *reinterpret_cast<float2*>(&hb[rr * 128 + cc]) =
                    make_float2(lk(acc[mt][nt][0]), lk(acc[mt][nt][1]));
                *reinterpret_cast<float2*>(&hb[(rr + 8) * 128 + cc]) =
                    make_float2(lk(acc[mt][nt][2]), lk(acc[mt][nt][3]));
            }
    }
    __syncthreads();

    // score pass + writeback: 4 threads per row, 32 cols each
    {
        int r = tid >> 2, seg = tid & 3;
        int gr = base + r;
        float4 p = make_float4(0.f, 0.f, 0.f, 0.f);
#pragma unroll
        for (int i = 0; i < 8; i++) {
            float4 v = *reinterpret_cast<const float4*>(&hb[r * 128 + seg * 32 + i * 4]);
            float ve[4] = {v.x, v.y, v.z, v.w};
#pragma unroll
            for (int e = 0; e < 4; e++) {
                float4 C = g_C[seg * 32 + i * 4 + e];
                p.x += ve[e] * C.x;
                p.y += ve[e] * C.y;
                p.z += ve[e] * C.z;
                p.w += ve[e] * C.w;
            }
            if (gr < N)
                *reinterpret_cast<float4*>(&g_h[(size_t)gr * TC + seg * 32 + i * 4]) = v;
        }
#pragma unroll
        for (int o = 1; o < 4; o <<= 1) {
            p.x += __shfl_down_sync(0xffffffffu, p.x, o, 4);
            p.y += __shfl_down_sync(0xffffffffu, p.y, o, 4);
            p.z += __shfl_down_sync(0xffffffffu, p.z, o, 4);
            p.w += __shfl_down_sync(0xffffffffu, p.w, o, 4);
        }
        if (seg == 0 && gr < N) g_sc4[gr] = p;
    }
}

// ---------------- K6: per-src gather + epilogue (one warp per node) ------
__global__ __launch_bounds__(256) void k_gather(float* __restrict__ out, int N) {
    int w = (blockIdx.x * blockDim.x + threadIdx.x) >> 5;
    int lane = threadIdx.x & 31;
    if (w >= N) return;
    int src = w;
    int beg = g_off[src], end = g_off[src + 1];

    float4 ss = g_sc4[src];
    float p0 = g_par[0], p1 = g_par[1];

    float ax = 0.f, ay = 0.f, az = 0.f, aw = 0.f;
    float rs_h = 0.f, rs_l = 0.f;

    for (int b = beg; b < end; b += 32) {
        int m = end - b;
        if (m > 32) m = 32;
        int d = 0;
        float eh = 0.f, el = 0.f;
        if (lane < m) {
            d = g_sorted[b + lane];
            float4 sd = g_sc4[d];
            eh = __expf(-lk((ss.x + sd.y) * p0));
            el = __expf(-lk((ss.z + sd.w) * p1));
        }
        for (int j = 0; j < m; j++) {
            int dj   = __shfl_sync(0xffffffffu, d, j);
            float ej = __shfl_sync(0xffffffffu, eh, j);
            float fj = __shfl_sync(0xffffffffu, el, j);
            float4 hv = *reinterpret_cast<const float4*>(&g_h[(size_t)dj * TC + lane * 4]);
            float wg = (lane < 16) ? ej : fj;
            ax += wg * hv.x;
            ay += wg * hv.y;
            az += wg * hv.z;
            aw += wg * hv.w;
            rs_h += ej;
            rs_l += fj;
        }
    }

    float denom = (lane < 16) ? (rs_h + g_par[2]) : (rs_l + g_par[3]);
    float inv = 1.0f / denom;
    float4 v;
    v.x = lk(ax * inv);
    v.y = lk(ay * inv);
    v.z = lk(az * inv);
    v.w = lk(aw * inv);
    *reinterpret_cast<float4*>(&out[(size_t)src * TC + lane * 4]) = v;
}

// ---------------- launch --------------------------------------------------
extern "C" void kernel_launch(void* const* d_in, const int* in_sizes, int n_in,
                              void* d_out, int out_size) {
    const float* input = (const float*)d_in[0];
    const int*   edge  = (const int*)d_in[1];
    const float* Wh    = (const float*)d_in[2];
    const float* Wl    = (const float*)d_in[3];
    const float* ah    = (const float*)d_in[4];
    const float* al    = (const float*)d_in[5];
    const float* ch    = (const float*)d_in[6];
    const float* cl    = (const float*)d_in[7];
    float* out = (float*)d_out;

    int N = in_sizes[0] / DIN;
    int E = in_sizes[1] / 2;
    int nb = (N + SCAN_B - 1) / SCAN_B;

    cudaFuncSetAttribute(k_mm, cudaFuncAttributeMaxDynamicSharedMemorySize, MM_SMEM);

    k_prep<<<1, 256>>>(ah, al, ch, cl);
    k_wprep<<<(DIN * TC + 255) / 256, 256>>>(Wh, Wl);
    k_zc<<<(N + 255) / 256, 256>>>(N);
    k_hist<<<(E + 255) / 256, 256>>>(edge, E);
    k_scan1<<<nb, SCAN_B>>>(N);
    k_scan2<<<1, 512>>>(nb);
    k_scan3<<<nb, SCAN_B>>>(N);
    k_scatter<<<(E + 255) / 256, 256>>>(edge, E);
    k_mm<<<(N + 127) / 128, 512, MM_SMEM>>>(input, N);
    k_gather<<<(N * 32 + 255) / 256, 256>>>(out, N);
}